// round 1
// baseline (speedup 1.0000x reference)
#include <cuda_runtime.h>
#include <cuda_bf16.h>
#include <math.h>
#include <float.h>
#include <stdint.h>

// ============================================================================
// Problem constants
// ============================================================================
#define DIMN   1024
#define HEADS  8
#define DH     64
#define HDH    512
#define SEQ    8192
#define BATCH  2
#define WIN    64
#define NW     128          // SEQ / WIN
#define NQ     1024
#define NKV    2048
#define ROWS   (BATCH * SEQ)          // 16384
#define QROWS  (BATCH * NQ)           // 2048
#define KVROWS (BATCH * NKV)          // 4096

// ============================================================================
// Device scratch (allocation-free rule: __device__ globals)
// ============================================================================
static __device__ __align__(16) float g_xn  [(size_t)ROWS * DIMN];     // layernormed x
static __device__ __align__(16) float g_qkv [(size_t)ROWS * 1536];     // light qkv
static __device__ __align__(16) float g_lo  [(size_t)ROWS * HDH];      // light attn out
static __device__ __align__(16) float g_s   [4 * SEQ];                 // [route*2+b][seq]
static __device__             int   g_idx_q [BATCH * NQ];
static __device__             int   g_idx_kv[BATCH * NKV];
static __device__             int   g_pos_q [BATCH * SEQ];
static __device__ __align__(16) float g_xq  [(size_t)QROWS * DIMN];
static __device__ __align__(16) float g_xkv [(size_t)KVROWS * DIMN];
static __device__ __align__(16) float g_qh  [(size_t)QROWS * HDH];
static __device__ __align__(16) float g_kvh [(size_t)KVROWS * DIMN];   // [row][h*128 + c]
static __device__ __align__(16) float g_oh  [(size_t)QROWS * HDH];
static __device__ __align__(16) float g_ho  [(size_t)QROWS * DIMN];    // heavy out

// ============================================================================
// Layernorm: g_xn = (x - m)/sqrt(v+1e-5)*g + b
// ============================================================================
__global__ void ln_kernel(const float* __restrict__ x,
                          const float* __restrict__ g,
                          const float* __restrict__ b) {
    int r = blockIdx.x;
    int tid = threadIdx.x;                 // 256
    const float* row = x + (size_t)r * DIMN;
    float4 v = *(const float4*)(row + tid * 4);
    __shared__ float red[256];
    float s = v.x + v.y + v.z + v.w;
    red[tid] = s; __syncthreads();
    for (int off = 128; off; off >>= 1) { if (tid < off) red[tid] += red[tid + off]; __syncthreads(); }
    float mean = red[0] * (1.0f / DIMN);
    __syncthreads();
    float d0 = v.x - mean, d1 = v.y - mean, d2 = v.z - mean, d3 = v.w - mean;
    red[tid] = d0*d0 + d1*d1 + d2*d2 + d3*d3; __syncthreads();
    for (int off = 128; off; off >>= 1) { if (tid < off) red[tid] += red[tid + off]; __syncthreads(); }
    float var = red[0] * (1.0f / DIMN);
    float inv = 1.0f / sqrtf(var + 1e-5f);
    int c = tid * 4;
    float4 o;
    o.x = d0 * inv * g[c+0] + b[c+0];
    o.y = d1 * inv * g[c+1] + b[c+1];
    o.z = d2 * inv * g[c+2] + b[c+2];
    o.w = d3 * inv * g[c+3] + b[c+3];
    *(float4*)(g_xn + (size_t)r * DIMN + c) = o;
}

// ============================================================================
// Routing scores: s[route][b][n] = dot(x[b,n,:], rt)
// one warp per row, both routes at once
// ============================================================================
__global__ void score_kernel(const float* __restrict__ x,
                             const float* __restrict__ rtq,
                             const float* __restrict__ rtkv) {
    int gw = (blockIdx.x * blockDim.x + threadIdx.x) >> 5;   // 0..16383
    int lane = threadIdx.x & 31;
    const float* row = x + (size_t)gw * DIMN;
    float aq = 0.f, akv = 0.f;
    for (int c = lane * 4; c < DIMN; c += 128) {
        float4 xv = *(const float4*)(row + c);
        float4 q  = *(const float4*)(rtq + c);
        float4 kv = *(const float4*)(rtkv + c);
        aq  += xv.x*q.x  + xv.y*q.y  + xv.z*q.z  + xv.w*q.w;
        akv += xv.x*kv.x + xv.y*kv.y + xv.z*kv.z + xv.w*kv.w;
    }
    for (int off = 16; off; off >>= 1) {
        aq  += __shfl_down_sync(0xffffffffu, aq,  off);
        akv += __shfl_down_sync(0xffffffffu, akv, off);
    }
    if (lane == 0) {
        int b = gw >> 13, n = gw & 8191;
        g_s[(0 * 2 + b) * SEQ + n] = aq;
        g_s[(2     + b) * SEQ + n] = akv;
    }
}

__global__ void fill_pos_kernel() {
    int i = blockIdx.x * blockDim.x + threadIdx.x;
    if (i < BATCH * SEQ) g_pos_q[i] = -1;
}

// ============================================================================
// Coor-descent + deterministic top-N selection. One block per (route,b).
// ============================================================================
__device__ __forceinline__ unsigned fmono(float x) {
    unsigned u = __float_as_uint(x);
    return (u & 0x80000000u) ? ~u : (u | 0x80000000u);
}

__device__ __forceinline__ int blk_reduce_sum_i(int v, int* buf, int tid) {
    buf[tid] = v; __syncthreads();
    for (int off = 512; off; off >>= 1) { if (tid < off) buf[tid] += buf[tid + off]; __syncthreads(); }
    int r = buf[0]; __syncthreads();
    return r;
}

__device__ __forceinline__ int blk_scan_excl(int v, int* buf, int tid, int* total) {
    buf[tid] = v; __syncthreads();
    for (int off = 1; off < 1024; off <<= 1) {
        int t = 0; if (tid >= off) t = buf[tid - off];
        __syncthreads();
        buf[tid] += t;
        __syncthreads();
    }
    int inc = buf[tid];
    *total = buf[1023];
    __syncthreads();
    return inc - v;
}

__global__ __launch_bounds__(1024) void coor_select_kernel() {
    int blk = blockIdx.x;                 // 0..3 == route*2 + b
    int route = blk >> 1, b = blk & 1;
    int N = route ? NKV : NQ;
    float logk = route ? logf(2304.0f) : logf(1152.0f);
    const float* srow = g_s + (size_t)blk * SEQ;

    __shared__ float ss[SEQ];     // 32KB
    __shared__ float fbuf[1024];  // 4KB
    __shared__ int   ibuf[1024];  // 4KB
    int tid = threadIdx.x;
    int i0 = tid * 8;

    for (int i = tid; i < SEQ; i += 1024) ss[i] = srow[i];
    __syncthreads();

    // global max of s
    float lm = -FLT_MAX;
    #pragma unroll
    for (int i = i0; i < i0 + 8; i++) lm = fmaxf(lm, ss[i]);
    fbuf[tid] = lm; __syncthreads();
    for (int off = 512; off; off >>= 1) { if (tid < off) fbuf[tid] = fmaxf(fbuf[tid], fbuf[tid + off]); __syncthreads(); }
    float smax = fbuf[0];
    __syncthreads();

    // coor descent: a1 special (b=-s => lse(0)=log(SEQ)), then 49 generic iters
    float a = logk - logf((float)SEQ);
    for (int it = 0; it < 49; it++) {
        float t = -a;
        float M = fminf(smax, t);
        float ls = 0.f;
        #pragma unroll
        for (int i = i0; i < i0 + 8; i++) ls += expf(fminf(ss[i], t) - M);
        fbuf[tid] = ls; __syncthreads();
        for (int off = 512; off; off >>= 1) { if (tid < off) fbuf[tid] += fbuf[tid + off]; __syncthreads(); }
        a = logk - (M + logf(fbuf[0]));
        __syncthreads();
    }

    // ---- selection ----
    int* idxArr = route ? &g_idx_kv[b * NKV] : &g_idx_q[b * NQ];

    int lc = 0;
    #pragma unroll
    for (int i = i0; i < i0 + 8; i++) lc += (ss[i] + a >= 0.0f);
    int C;
    int exc = blk_scan_excl(lc, ibuf, tid, &C);

    if (C >= N) {
        int r = exc;
        for (int i = i0; i < i0 + 8; i++) {
            if (ss[i] + a >= 0.0f) {
                if (r < N) { idxArr[r] = i; if (!route) g_pos_q[b * SEQ + i] = r; }
                r++;
            }
        }
    } else {
        int r = exc;
        for (int i = i0; i < i0 + 8; i++) {
            if (ss[i] + a >= 0.0f) {
                idxArr[r] = i; if (!route) g_pos_q[b * SEQ + i] = r;
                r++;
            }
        }
        int R = N - C;
        // radix-select the R-th largest among unflagged (monotone uint bits)
        unsigned ans = 0;
        for (int bit = 31; bit >= 0; bit--) {
            unsigned cand = ans | (1u << bit);
            int c = 0;
            for (int i = i0; i < i0 + 8; i++)
                if (ss[i] + a < 0.0f && fmono(ss[i]) >= cand) c++;
            int tot = blk_reduce_sum_i(c, ibuf, tid);
            if (tot >= R) ans = cand;
        }
        // strictly greater than ans
        int lcGT = 0;
        for (int i = i0; i < i0 + 8; i++)
            if (ss[i] + a < 0.0f && fmono(ss[i]) > ans) lcGT++;
        int totGT;
        int excGT = blk_scan_excl(lcGT, ibuf, tid, &totGT);
        {
            int rr = C + excGT;
            for (int i = i0; i < i0 + 8; i++)
                if (ss[i] + a < 0.0f && fmono(ss[i]) > ans) {
                    idxArr[rr] = i; if (!route) g_pos_q[b * SEQ + i] = rr;
                    rr++;
                }
        }
        // equal to ans: lowest indices first
        int lcEQ = 0;
        for (int i = i0; i < i0 + 8; i++)
            if (ss[i] + a < 0.0f && fmono(ss[i]) == ans) lcEQ++;
        int totEQ;
        int excEQ = blk_scan_excl(lcEQ, ibuf, tid, &totEQ);
        int need = R - totGT;
        int r2 = excEQ;
        for (int i = i0; i < i0 + 8; i++)
            if (ss[i] + a < 0.0f && fmono(ss[i]) == ans) {
                if (r2 < need) {
                    int rank = C + totGT + r2;
                    idxArr[rank] = i; if (!route) g_pos_q[b * SEQ + i] = rank;
                }
                r2++;
            }
    }
}

// ============================================================================
// SGEMM: C = A(MxK, rowmajor) * B(KxN, rowmajor). M%128==0, N%128==0, K%8==0
// 128x128 tile, 256 threads, 8x8 microtile
// ============================================================================
__global__ __launch_bounds__(256) void sgemm_kernel(const float* __restrict__ A,
                                                    const float* __restrict__ B,
                                                    float* __restrict__ C,
                                                    int M, int N, int K) {
    __shared__ __align__(16) float As[8][128];
    __shared__ __align__(16) float Bs[8][128];
    int tid = threadIdx.x;
    int tx = tid & 15, ty = tid >> 4;
    int bm = blockIdx.y * 128, bn = blockIdx.x * 128;

    int arow = tid >> 1;
    int acol = (tid & 1) * 4;
    int brow = tid >> 5;
    int bcol = (tid & 31) * 4;
    const float* Aptr = A + (size_t)(bm + arow) * K + acol;
    const float* Bptr = B + (size_t)brow * N + bn + bcol;

    float acc[8][8];
    #pragma unroll
    for (int i = 0; i < 8; i++)
        #pragma unroll
        for (int j = 0; j < 8; j++) acc[i][j] = 0.f;

    for (int k0 = 0; k0 < K; k0 += 8) {
        float4 av = *(const float4*)(Aptr + k0);
        float4 bv = *(const float4*)(Bptr + (size_t)k0 * N);
        __syncthreads();
        As[acol + 0][arow] = av.x;
        As[acol + 1][arow] = av.y;
        As[acol + 2][arow] = av.z;
        As[acol + 3][arow] = av.w;
        *(float4*)&Bs[brow][bcol] = bv;
        __syncthreads();
        #pragma unroll
        for (int kk = 0; kk < 8; kk++) {
            float4 a0 = *(const float4*)&As[kk][ty * 8];
            float4 a1 = *(const float4*)&As[kk][ty * 8 + 4];
            float4 b0 = *(const float4*)&Bs[kk][tx * 8];
            float4 b1 = *(const float4*)&Bs[kk][tx * 8 + 4];
            float ar[8] = {a0.x, a0.y, a0.z, a0.w, a1.x, a1.y, a1.z, a1.w};
            float br[8] = {b0.x, b0.y, b0.z, b0.w, b1.x, b1.y, b1.z, b1.w};
            #pragma unroll
            for (int i = 0; i < 8; i++)
                #pragma unroll
                for (int j = 0; j < 8; j++) acc[i][j] += ar[i] * br[j];
        }
    }

    #pragma unroll
    for (int i = 0; i < 8; i++) {
        size_t off = (size_t)(bm + ty * 8 + i) * N + bn + tx * 8;
        *(float4*)(C + off)     = make_float4(acc[i][0], acc[i][1], acc[i][2], acc[i][3]);
        *(float4*)(C + off + 4) = make_float4(acc[i][4], acc[i][5], acc[i][6], acc[i][7]);
    }
}

// ============================================================================
// Online-softmax key step shared by both attention kernels
// ============================================================================
__device__ __forceinline__ void attn_key(const float* __restrict__ kr,
                                         const float* __restrict__ vr,
                                         const float4* qv, float4* o,
                                         float& m, float& z) {
    const float4* k4 = (const float4*)kr;
    const float4* v4 = (const float4*)vr;
    float s0 = 0.f, s1 = 0.f, s2 = 0.f, s3 = 0.f;
    #pragma unroll
    for (int d = 0; d < 16; d++) {
        float4 k = k4[d];
        s0 += qv[d].x * k.x; s1 += qv[d].y * k.y;
        s2 += qv[d].z * k.z; s3 += qv[d].w * k.w;
    }
    float sim = (s0 + s1) + (s2 + s3);
    if (sim > m) {
        float c = expf(m - sim);
        z *= c;
        #pragma unroll
        for (int d = 0; d < 16; d++) { o[d].x *= c; o[d].y *= c; o[d].z *= c; o[d].w *= c; }
        m = sim;
    }
    float w = expf(sim - m);
    z += w;
    #pragma unroll
    for (int d = 0; d < 16; d++) {
        float4 v = v4[d];
        o[d].x += w * v.x; o[d].y += w * v.y; o[d].z += w * v.z; o[d].w += w * v.w;
    }
}

// ============================================================================
// Light (windowed) attention: thread per query, unit = (b,h,w), 4 units/block
// ============================================================================
__global__ __launch_bounds__(256) void light_attn_kernel() {
    int unit = blockIdx.x * 4 + (threadIdx.x >> 6);   // 0..2047
    int qi = threadIdx.x & 63;
    int w = unit & 127;
    int h = (unit >> 7) & 7;
    int b = unit >> 10;
    size_t nbase = (size_t)b * SEQ + (size_t)w * WIN;

    const float4* qp = (const float4*)(g_qkv + (nbase + qi) * 1536 + h * 64);
    float4 qv[16];
    #pragma unroll
    for (int d = 0; d < 16; d++) {
        float4 q = qp[d];
        qv[d] = make_float4(q.x * 0.125f, q.y * 0.125f, q.z * 0.125f, q.w * 0.125f);
    }
    float4 o[16];
    #pragma unroll
    for (int d = 0; d < 16; d++) o[d] = make_float4(0.f, 0.f, 0.f, 0.f);
    float m = -FLT_MAX, z = 0.f;

    int ws = (w > 0) ? -1 : 0;
    int we = (w < NW - 1) ? 1 : 0;
    for (int dw = ws; dw <= we; dw++) {
        size_t kb = (nbase + (size_t)dw * WIN) * 1536 + 512 + h * 64;
        for (int j = 0; j < WIN; j++) {
            const float* kr = g_qkv + kb + (size_t)j * 1536;
            attn_key(kr, kr + 512, qv, o, m, z);
        }
    }
    float inv = 1.0f / z;
    float4* op = (float4*)(g_lo + (nbase + qi) * HDH + h * 64);
    #pragma unroll
    for (int d = 0; d < 16; d++)
        op[d] = make_float4(o[d].x * inv, o[d].y * inv, o[d].z * inv, o[d].w * inv);
}

// ============================================================================
// Gather + rmsnorm: rows 0..2047 -> xq, rows 2048..6143 -> xkv
// ============================================================================
__global__ void gather_rms_kernel(const float* __restrict__ x,
                                  const float* __restrict__ rms_g) {
    int r = blockIdx.x;
    int tid = threadIdx.x;           // 256
    const float* src;
    float* dst;
    if (r < QROWS) {
        int b = r >> 10;
        int srcn = g_idx_q[r];
        src = x + ((size_t)b * SEQ + srcn) * DIMN;
        dst = g_xq + (size_t)r * DIMN;
    } else {
        int r2 = r - QROWS;
        int b = r2 >> 11;
        int srcn = g_idx_kv[r2];
        src = x + ((size_t)b * SEQ + srcn) * DIMN;
        dst = g_xkv + (size_t)r2 * DIMN;
    }
    int c = tid * 4;
    float4 v = *(const float4*)(src + c);
    __shared__ float red[256];
    red[tid] = v.x*v.x + v.y*v.y + v.z*v.z + v.w*v.w;
    __syncthreads();
    for (int off = 128; off; off >>= 1) { if (tid < off) red[tid] += red[tid + off]; __syncthreads(); }
    float nrm = fmaxf(sqrtf(red[0]), 1e-12f);
    float scale = 32.0f / nrm;
    float4 o;
    o.x = v.x * scale * rms_g[c+0];
    o.y = v.y * scale * rms_g[c+1];
    o.z = v.z * scale * rms_g[c+2];
    o.w = v.w * scale * rms_g[c+3];
    *(float4*)(dst + c) = o;
}

// ============================================================================
// Heavy attention: 2049 keys (null + 2048), thread per query
// ============================================================================
__global__ __launch_bounds__(128) void heavy_attn_kernel(const float* __restrict__ null_kv) {
    int b = blockIdx.z, h = blockIdx.y;
    int q = blockIdx.x * 128 + threadIdx.x;

    const float4* qp = (const float4*)(g_qh + ((size_t)(b * NQ + q)) * HDH + h * 64);
    float4 qv[16];
    #pragma unroll
    for (int d = 0; d < 16; d++) {
        float4 t = qp[d];
        qv[d] = make_float4(t.x * 0.125f, t.y * 0.125f, t.z * 0.125f, t.w * 0.125f);
    }
    float4 o[16];
    #pragma unroll
    for (int d = 0; d < 16; d++) o[d] = make_float4(0.f, 0.f, 0.f, 0.f);
    float m = -FLT_MAX, z = 0.f;

    // null key first (matches reference concat order)
    attn_key(null_kv + h * 64, null_kv + HDH + h * 64, qv, o, m, z);

    for (int n = 0; n < NKV; n++) {
        const float* kr = g_kvh + ((size_t)(b * NKV + n)) * DIMN + h * 128;
        attn_key(kr, kr + 64, qv, o, m, z);
    }
    float inv = 1.0f / z;
    float4* op = (float4*)(g_oh + ((size_t)(b * NQ + q)) * HDH + h * 64);
    #pragma unroll
    for (int d = 0; d < 16; d++)
        op[d] = make_float4(o[d].x * inv, o[d].y * inv, o[d].z * inv, o[d].w * inv);
}

// ============================================================================
// Combine: out = light (already in d_out) + (selected ? heavy : null_q)
// ============================================================================
__global__ void combine_kernel(float* __restrict__ out,
                               const float* __restrict__ null_q) {
    int r = blockIdx.x;              // 0..16383
    int b = r >> 13;
    int pos = g_pos_q[r];
    int c = threadIdx.x * 4;
    float4 v = *(const float4*)(out + (size_t)r * DIMN + c);
    float4 addv;
    if (pos >= 0)
        addv = *(const float4*)(g_ho + ((size_t)(b * NQ + pos)) * DIMN + c);
    else
        addv = *(const float4*)(null_q + c);
    v.x += addv.x; v.y += addv.y; v.z += addv.z; v.w += addv.w;
    *(float4*)(out + (size_t)r * DIMN + c) = v;
}

// ============================================================================
// Launch
// ============================================================================
extern "C" void kernel_launch(void* const* d_in, const int* in_sizes, int n_in,
                              void* d_out, int out_size) {
    (void)in_sizes; (void)n_in; (void)out_size;
    const float* x       = (const float*)d_in[0];
    const float* ln_g    = (const float*)d_in[1];
    const float* ln_b    = (const float*)d_in[2];
    const float* w_qkv_l = (const float*)d_in[3];
    const float* w_out_l = (const float*)d_in[4];
    const float* null_q  = (const float*)d_in[5];
    const float* rt_q    = (const float*)d_in[6];
    const float* rt_kv   = (const float*)d_in[7];
    const float* rms_g   = (const float*)d_in[8];
    const float* w_q_h   = (const float*)d_in[9];
    const float* w_kv_h  = (const float*)d_in[10];
    const float* null_kv = (const float*)d_in[11];
    const float* w_out_h = (const float*)d_in[12];
    float* out = (float*)d_out;

    // device-global pointers (kernels reference globals directly; need symbol
    // addresses only where passed — here kernels use globals, so nothing to fetch)

    // 1. layernorm
    ln_kernel<<<ROWS, 256>>>(x, ln_g, ln_b);
    // 2. routing scores
    score_kernel<<<2048, 256>>>(x, rt_q, rt_kv);
    // 3. init pos map
    fill_pos_kernel<<<(BATCH * SEQ + 1023) / 1024, 1024>>>();
    // 4. coor descent + top-N selection
    coor_select_kernel<<<4, 1024>>>();
    // 5. light qkv GEMM: (16384x1024) @ (1024x1536)
    {
        float* qkv;      cudaGetSymbolAddress((void**)&qkv, g_qkv);
        float* xn;       cudaGetSymbolAddress((void**)&xn, g_xn);
        sgemm_kernel<<<dim3(1536 / 128, ROWS / 128), 256>>>(xn, w_qkv_l, qkv, ROWS, 1536, DIMN);
    }
    // 6. light windowed attention
    light_attn_kernel<<<512, 256>>>();
    // 7. light out GEMM -> d_out : (16384x512) @ (512x1024)
    {
        float* lo; cudaGetSymbolAddress((void**)&lo, g_lo);
        sgemm_kernel<<<dim3(DIMN / 128, ROWS / 128), 256>>>(lo, w_out_l, out, ROWS, DIMN, HDH);
    }
    // 8. gather + rmsnorm
    gather_rms_kernel<<<QROWS + KVROWS, 256>>>(x, rms_g);
    // 9. heavy q GEMM: (2048x1024) @ (1024x512)
    {
        float* xq; cudaGetSymbolAddress((void**)&xq, g_xq);
        float* qh; cudaGetSymbolAddress((void**)&qh, g_qh);
        sgemm_kernel<<<dim3(HDH / 128, QROWS / 128), 256>>>(xq, w_q_h, qh, QROWS, HDH, DIMN);
    }
    // 10. heavy kv GEMM: (4096x1024) @ (1024x1024)
    {
        float* xkv; cudaGetSymbolAddress((void**)&xkv, g_xkv);
        float* kvh; cudaGetSymbolAddress((void**)&kvh, g_kvh);
        sgemm_kernel<<<dim3(DIMN / 128, KVROWS / 128), 256>>>(xkv, w_kv_h, kvh, KVROWS, DIMN, DIMN);
    }
    // 11. heavy attention
    heavy_attn_kernel<<<dim3(NQ / 128, HEADS, BATCH), 128>>>(null_kv);
    // 12. heavy out GEMM: (2048x512) @ (512x1024)
    {
        float* oh; cudaGetSymbolAddress((void**)&oh, g_oh);
        float* ho; cudaGetSymbolAddress((void**)&ho, g_ho);
        sgemm_kernel<<<dim3(DIMN / 128, QROWS / 128), 256>>>(oh, w_out_h, ho, QROWS, DIMN, HDH);
    }
    // 13. combine
    combine_kernel<<<ROWS, 256>>>(out, null_q);
}

// round 3
// speedup vs baseline: 1.3477x; 1.3477x over previous
#include <cuda_runtime.h>
#include <cuda_bf16.h>
#include <math.h>
#include <float.h>
#include <stdint.h>

// ============================================================================
// Problem constants
// ============================================================================
#define DIMN   1024
#define HEADS  8
#define DH     64
#define HDH    512
#define SEQ    8192
#define BATCH  2
#define WIN    64
#define NW     128
#define NQ     1024
#define NKV    2048
#define ROWS   (BATCH * SEQ)          // 16384
#define QROWS  (BATCH * NQ)           // 2048
#define KVROWS (BATCH * NKV)          // 4096

// ============================================================================
// Device scratch
// ============================================================================
static __device__ __align__(16) float g_xn  [(size_t)ROWS * DIMN];
static __device__ __align__(16) float g_qkv [(size_t)ROWS * 1536];
static __device__ __align__(16) float g_lo  [(size_t)ROWS * HDH];
static __device__ __align__(16) float g_s   [4 * SEQ];
static __device__             int   g_idx_q [BATCH * NQ];
static __device__             int   g_idx_kv[BATCH * NKV];
static __device__             int   g_pos_q [BATCH * SEQ];
static __device__ __align__(16) float g_xq  [(size_t)QROWS * DIMN];
static __device__ __align__(16) float g_xkv [(size_t)KVROWS * DIMN];
static __device__ __align__(16) float g_qh  [(size_t)QROWS * HDH];
static __device__ __align__(16) float g_kvh [(size_t)KVROWS * DIMN];
static __device__ __align__(16) float g_oh  [(size_t)QROWS * HDH];
static __device__ __align__(16) float g_ho  [(size_t)QROWS * DIMN];
// bf16-split operand scratch (reused sequentially by all 5 GEMMs)
static __device__ __align__(16) __nv_bfloat16 g_ahi[(size_t)ROWS * DIMN];
static __device__ __align__(16) __nv_bfloat16 g_alo[(size_t)ROWS * DIMN];
static __device__ __align__(16) __nv_bfloat16 g_bhi[(size_t)1536 * DIMN];
static __device__ __align__(16) __nv_bfloat16 g_blo[(size_t)1536 * DIMN];

// ============================================================================
// PTX helpers (base sm_100-safe: ldmatrix / mma.sync / cp.async only)
// ============================================================================
__device__ __forceinline__ uint32_t smem_u32(const void* p) {
    uint32_t a;
    asm("{ .reg .u64 t; cvta.to.shared.u64 t, %1; cvt.u32.u64 %0, t; }" : "=r"(a) : "l"(p));
    return a;
}
#define LDMX4(r, addr) \
    asm volatile("ldmatrix.sync.aligned.m8n8.x4.shared.b16 {%0,%1,%2,%3}, [%4];" \
        : "=r"((r)[0]), "=r"((r)[1]), "=r"((r)[2]), "=r"((r)[3]) : "r"(addr))
#define MMA16816(d, a, b) \
    asm volatile("mma.sync.aligned.m16n8k16.row.col.f32.bf16.bf16.f32 " \
        "{%0,%1,%2,%3}, {%4,%5,%6,%7}, {%8,%9}, {%0,%1,%2,%3};" \
        : "+f"((d)[0]), "+f"((d)[1]), "+f"((d)[2]), "+f"((d)[3]) \
        : "r"((a)[0]), "r"((a)[1]), "r"((a)[2]), "r"((a)[3]), "r"((b)[0]), "r"((b)[1]))
#define CP_ASYNC16(dst, src) \
    asm volatile("cp.async.cg.shared.global [%0], [%1], 16;" :: "r"(dst), "l"(src))
#define CP_COMMIT()  asm volatile("cp.async.commit_group;")
#define CP_WAIT(n)   asm volatile("cp.async.wait_group %0;" :: "n"(n))

// ============================================================================
// fp32 -> bf16 (hi, lo) split conversions
// ============================================================================
__global__ void convA_kernel(const float* __restrict__ A,
                             __nv_bfloat16* __restrict__ hi,
                             __nv_bfloat16* __restrict__ lo, int n8) {
    int i = blockIdx.x * blockDim.x + threadIdx.x;
    if (i >= n8) return;
    float4 v0 = ((const float4*)A)[2 * i];
    float4 v1 = ((const float4*)A)[2 * i + 1];
    float v[8] = {v0.x, v0.y, v0.z, v0.w, v1.x, v1.y, v1.z, v1.w};
    __align__(16) __nv_bfloat16 h[8];
    __align__(16) __nv_bfloat16 l[8];
    #pragma unroll
    for (int j = 0; j < 8; j++) {
        h[j] = __float2bfloat16_rn(v[j]);
        l[j] = __float2bfloat16_rn(v[j] - __bfloat162float(h[j]));
    }
    ((uint4*)hi)[i] = *(const uint4*)h;
    ((uint4*)lo)[i] = *(const uint4*)l;
}

// B (KxN rowmajor fp32) -> transposed [N][K] bf16 hi/lo
__global__ void convBT_kernel(const float* __restrict__ B,
                              __nv_bfloat16* __restrict__ hi,
                              __nv_bfloat16* __restrict__ lo, int K, int N) {
    __shared__ float t[32][33];
    int n0 = blockIdx.x * 32, k0 = blockIdx.y * 32;
    int tx = threadIdx.x, ty = threadIdx.y;   // (32, 8)
    #pragma unroll
    for (int i = ty; i < 32; i += 8)
        t[i][tx] = B[(size_t)(k0 + i) * N + n0 + tx];
    __syncthreads();
    #pragma unroll
    for (int i = ty; i < 32; i += 8) {
        float v = t[tx][i];                    // B[k0+tx][n0+i]
        __nv_bfloat16 h = __float2bfloat16_rn(v);
        __nv_bfloat16 l = __float2bfloat16_rn(v - __bfloat162float(h));
        hi[(size_t)(n0 + i) * K + k0 + tx] = h;
        lo[(size_t)(n0 + i) * K + k0 + tx] = l;
    }
}

// ============================================================================
// mma.sync bf16-split GEMM: C(fp32 MxN) = A(MxK) @ B(KxN)
// A as hi/lo bf16 [M][K]; B as hi/lo bf16 [N][K] (pre-transposed).
// Block tile 128x128, 8 warps (4x2), warp tile 32x64, K-step 32,
// double-buffered cp.async. Padded smem stride 40 halves (conflict-free).
// ============================================================================
#define KSTEP    32
#define SSTR     40                    // halves per row (32 + 8 pad)
#define MATB     (128 * SSTR * 2)      // 10240 bytes per matrix tile
#define BUFB     (4 * MATB)            // 40960 per stage
#define GEMM_SMEM (2 * BUFB)           // 81920

__device__ __forceinline__ void gemm_prefetch(
    const __nv_bfloat16* __restrict__ Ahi, const __nv_bfloat16* __restrict__ Alo,
    const __nv_bfloat16* __restrict__ Bhi, const __nv_bfloat16* __restrict__ Blo,
    int bm, int bn, int K, int k0, uint32_t bufbase, int tid) {
    #pragma unroll
    for (int c = tid; c < 2048; c += 256) {
        int mat = c >> 9;           // 0..3
        int cc  = c & 511;
        int row = cc >> 2;
        int kc  = (cc & 3) * 8;     // halves
        const __nv_bfloat16* src;
        int rbase;
        if      (mat == 0) { src = Ahi; rbase = bm; }
        else if (mat == 1) { src = Alo; rbase = bm; }
        else if (mat == 2) { src = Bhi; rbase = bn; }
        else               { src = Blo; rbase = bn; }
        const void* gsrc = src + (size_t)(rbase + row) * K + k0 + kc;
        uint32_t dst = bufbase + mat * MATB + row * (SSTR * 2) + kc * 2;
        CP_ASYNC16(dst, gsrc);
    }
    CP_COMMIT();
}

__global__ __launch_bounds__(256) void mma_gemm_kernel(
    const __nv_bfloat16* __restrict__ Ahi, const __nv_bfloat16* __restrict__ Alo,
    const __nv_bfloat16* __restrict__ Bhi, const __nv_bfloat16* __restrict__ Blo,
    float* __restrict__ C, int M, int N, int K) {
    extern __shared__ __align__(16) char smem[];
    uint32_t sb = smem_u32(smem);
    int tid = threadIdx.x;
    int lane = tid & 31, w = tid >> 5;
    int wm = w & 3, wn = w >> 2;               // warp tile origin (wm*32, wn*64)
    int bm = blockIdx.y * 128, bn = blockIdx.x * 128;

    float acc[2][8][4];
    #pragma unroll
    for (int i = 0; i < 2; i++)
        #pragma unroll
        for (int j = 0; j < 8; j++)
            #pragma unroll
            for (int q = 0; q < 4; q++) acc[i][j][q] = 0.f;

    // ldmatrix lane addressing (within a 16x16 / 16x(2x8) tile)
    int a_row = lane & 15,               a_kof = (lane >> 4) * 8;
    int b_row = ((lane >> 4) & 1) * 8 + (lane & 7), b_kof = ((lane >> 3) & 1) * 8;

    gemm_prefetch(Ahi, Alo, Bhi, Blo, bm, bn, K, 0, sb, tid);
    int nt = K / KSTEP;
    for (int t = 0; t < nt; t++) {
        if (t + 1 < nt) {
            gemm_prefetch(Ahi, Alo, Bhi, Blo, bm, bn, K, (t + 1) * KSTEP,
                          sb + ((t + 1) & 1) * BUFB, tid);
            CP_WAIT(1);
        } else {
            CP_WAIT(0);
        }
        __syncthreads();
        uint32_t buf = sb + (t & 1) * BUFB;
        #pragma unroll
        for (int ks = 0; ks < 2; ks++) {
            int kk = ks * 16;
            uint32_t ah[2][4], al[2][4];
            #pragma unroll
            for (int mi = 0; mi < 2; mi++) {
                int row = wm * 32 + mi * 16 + a_row;
                uint32_t off = row * (SSTR * 2) + (kk + a_kof) * 2;
                LDMX4(ah[mi], buf + 0 * MATB + off);
                LDMX4(al[mi], buf + 1 * MATB + off);
            }
            #pragma unroll
            for (int jp = 0; jp < 4; jp++) {
                int row = wn * 64 + jp * 16 + b_row;
                uint32_t off = row * (SSTR * 2) + (kk + b_kof) * 2;
                uint32_t rh[4], rl[4];
                LDMX4(rh, buf + 2 * MATB + off);
                LDMX4(rl, buf + 3 * MATB + off);
                uint32_t bh0[2] = {rh[0], rh[1]}, bh1[2] = {rh[2], rh[3]};
                uint32_t bl0[2] = {rl[0], rl[1]}, bl1[2] = {rl[2], rl[3]};
                #pragma unroll
                for (int mi = 0; mi < 2; mi++) {
                    MMA16816(acc[mi][jp * 2    ], ah[mi], bh0);
                    MMA16816(acc[mi][jp * 2    ], ah[mi], bl0);
                    MMA16816(acc[mi][jp * 2    ], al[mi], bh0);
                    MMA16816(acc[mi][jp * 2 + 1], ah[mi], bh1);
                    MMA16816(acc[mi][jp * 2 + 1], ah[mi], bl1);
                    MMA16816(acc[mi][jp * 2 + 1], al[mi], bh1);
                }
            }
        }
        __syncthreads();
    }

    // epilogue
    int g = lane >> 2, tig = lane & 3;
    #pragma unroll
    for (int mi = 0; mi < 2; mi++) {
        int r0 = bm + wm * 32 + mi * 16 + g;
        #pragma unroll
        for (int nj = 0; nj < 8; nj++) {
            int col = bn + wn * 64 + nj * 8 + tig * 2;
            *(float2*)(C + (size_t)r0 * N + col)       = make_float2(acc[mi][nj][0], acc[mi][nj][1]);
            *(float2*)(C + (size_t)(r0 + 8) * N + col) = make_float2(acc[mi][nj][2], acc[mi][nj][3]);
        }
    }
}

// ============================================================================
// Layernorm
// ============================================================================
__global__ void ln_kernel(const float* __restrict__ x,
                          const float* __restrict__ g,
                          const float* __restrict__ b) {
    int r = blockIdx.x;
    int tid = threadIdx.x;
    const float* row = x + (size_t)r * DIMN;
    float4 v = *(const float4*)(row + tid * 4);
    __shared__ float red[256];
    float s = v.x + v.y + v.z + v.w;
    red[tid] = s; __syncthreads();
    for (int off = 128; off; off >>= 1) { if (tid < off) red[tid] += red[tid + off]; __syncthreads(); }
    float mean = red[0] * (1.0f / DIMN);
    __syncthreads();
    float d0 = v.x - mean, d1 = v.y - mean, d2 = v.z - mean, d3 = v.w - mean;
    red[tid] = d0*d0 + d1*d1 + d2*d2 + d3*d3; __syncthreads();
    for (int off = 128; off; off >>= 1) { if (tid < off) red[tid] += red[tid + off]; __syncthreads(); }
    float var = red[0] * (1.0f / DIMN);
    float inv = 1.0f / sqrtf(var + 1e-5f);
    int c = tid * 4;
    float4 o;
    o.x = d0 * inv * g[c+0] + b[c+0];
    o.y = d1 * inv * g[c+1] + b[c+1];
    o.z = d2 * inv * g[c+2] + b[c+2];
    o.w = d3 * inv * g[c+3] + b[c+3];
    *(float4*)(g_xn + (size_t)r * DIMN + c) = o;
}

// ============================================================================
// Routing scores
// ============================================================================
__global__ void score_kernel(const float* __restrict__ x,
                             const float* __restrict__ rtq,
                             const float* __restrict__ rtkv) {
    int gw = (blockIdx.x * blockDim.x + threadIdx.x) >> 5;
    int lane = threadIdx.x & 31;
    const float* row = x + (size_t)gw * DIMN;
    float aq = 0.f, akv = 0.f;
    for (int c = lane * 4; c < DIMN; c += 128) {
        float4 xv = *(const float4*)(row + c);
        float4 q  = *(const float4*)(rtq + c);
        float4 kv = *(const float4*)(rtkv + c);
        aq  += xv.x*q.x  + xv.y*q.y  + xv.z*q.z  + xv.w*q.w;
        akv += xv.x*kv.x + xv.y*kv.y + xv.z*kv.z + xv.w*kv.w;
    }
    for (int off = 16; off; off >>= 1) {
        aq  += __shfl_down_sync(0xffffffffu, aq,  off);
        akv += __shfl_down_sync(0xffffffffu, akv, off);
    }
    if (lane == 0) {
        int b = gw >> 13, n = gw & 8191;
        g_s[(0 * 2 + b) * SEQ + n] = aq;
        g_s[(2     + b) * SEQ + n] = akv;
    }
}

__global__ void fill_pos_kernel() {
    int i = blockIdx.x * blockDim.x + threadIdx.x;
    if (i < BATCH * SEQ) g_pos_q[i] = -1;
}

// ============================================================================
// Coor-descent + deterministic top-N selection
// ============================================================================
__device__ __forceinline__ unsigned fmono(float x) {
    unsigned u = __float_as_uint(x);
    return (u & 0x80000000u) ? ~u : (u | 0x80000000u);
}
__device__ __forceinline__ int blk_reduce_sum_i(int v, int* buf, int tid) {
    buf[tid] = v; __syncthreads();
    for (int off = 512; off; off >>= 1) { if (tid < off) buf[tid] += buf[tid + off]; __syncthreads(); }
    int r = buf[0]; __syncthreads();
    return r;
}
__device__ __forceinline__ int blk_scan_excl(int v, int* buf, int tid, int* total) {
    buf[tid] = v; __syncthreads();
    for (int off = 1; off < 1024; off <<= 1) {
        int t = 0; if (tid >= off) t = buf[tid - off];
        __syncthreads();
        buf[tid] += t;
        __syncthreads();
    }
    int inc = buf[tid];
    *total = buf[1023];
    __syncthreads();
    return inc - v;
}

__global__ __launch_bounds__(1024) void coor_select_kernel() {
    int blk = blockIdx.x;
    int route = blk >> 1, b = blk & 1;
    int N = route ? NKV : NQ;
    float logk = route ? logf(2304.0f) : logf(1152.0f);
    const float* srow = g_s + (size_t)blk * SEQ;

    __shared__ float ss[SEQ];
    __shared__ float fbuf[1024];
    __shared__ int   ibuf[1024];
    int tid = threadIdx.x;
    int i0 = tid * 8;

    for (int i = tid; i < SEQ; i += 1024) ss[i] = srow[i];
    __syncthreads();

    float lm = -FLT_MAX;
    #pragma unroll
    for (int i = i0; i < i0 + 8; i++) lm = fmaxf(lm, ss[i]);
    fbuf[tid] = lm; __syncthreads();
    for (int off = 512; off; off >>= 1) { if (tid < off) fbuf[tid] = fmaxf(fbuf[tid], fbuf[tid + off]); __syncthreads(); }
    float smax = fbuf[0];
    __syncthreads();

    float a = logk - logf((float)SEQ);
    for (int it = 0; it < 49; it++) {
        float t = -a;
        float M = fminf(smax, t);
        float ls = 0.f;
        #pragma unroll
        for (int i = i0; i < i0 + 8; i++) ls += expf(fminf(ss[i], t) - M);
        fbuf[tid] = ls; __syncthreads();
        for (int off = 512; off; off >>= 1) { if (tid < off) fbuf[tid] += fbuf[tid + off]; __syncthreads(); }
        a = logk - (M + logf(fbuf[0]));
        __syncthreads();
    }

    int* idxArr = route ? &g_idx_kv[b * NKV] : &g_idx_q[b * NQ];

    int lc = 0;
    #pragma unroll
    for (int i = i0; i < i0 + 8; i++) lc += (ss[i] + a >= 0.0f);
    int C;
    int exc = blk_scan_excl(lc, ibuf, tid, &C);

    if (C >= N) {
        int r = exc;
        for (int i = i0; i < i0 + 8; i++) {
            if (ss[i] + a >= 0.0f) {
                if (r < N) { idxArr[r] = i; if (!route) g_pos_q[b * SEQ + i] = r; }
                r++;
            }
        }
    } else {
        int r = exc;
        for (int i = i0; i < i0 + 8; i++) {
            if (ss[i] + a >= 0.0f) {
                idxArr[r] = i; if (!route) g_pos_q[b * SEQ + i] = r;
                r++;
            }
        }
        int R = N - C;
        unsigned ans = 0;
        for (int bit = 31; bit >= 0; bit--) {
            unsigned cand = ans | (1u << bit);
            int c = 0;
            for (int i = i0; i < i0 + 8; i++)
                if (ss[i] + a < 0.0f && fmono(ss[i]) >= cand) c++;
            int tot = blk_reduce_sum_i(c, ibuf, tid);
            if (tot >= R) ans = cand;
        }
        int lcGT = 0;
        for (int i = i0; i < i0 + 8; i++)
            if (ss[i] + a < 0.0f && fmono(ss[i]) > ans) lcGT++;
        int totGT;
        int excGT = blk_scan_excl(lcGT, ibuf, tid, &totGT);
        {
            int rr = C + excGT;
            for (int i = i0; i < i0 + 8; i++)
                if (ss[i] + a < 0.0f && fmono(ss[i]) > ans) {
                    idxArr[rr] = i; if (!route) g_pos_q[b * SEQ + i] = rr;
                    rr++;
                }
        }
        int lcEQ = 0;
        for (int i = i0; i < i0 + 8; i++)
            if (ss[i] + a < 0.0f && fmono(ss[i]) == ans) lcEQ++;
        int totEQ;
        int excEQ = blk_scan_excl(lcEQ, ibuf, tid, &totEQ);
        int need = R - totGT;
        int r2 = excEQ;
        for (int i = i0; i < i0 + 8; i++)
            if (ss[i] + a < 0.0f && fmono(ss[i]) == ans) {
                if (r2 < need) {
                    int rank = C + totGT + r2;
                    idxArr[rank] = i; if (!route) g_pos_q[b * SEQ + i] = rank;
                }
                r2++;
            }
    }
}

// ============================================================================
// Online-softmax shared step
// ============================================================================
__device__ __forceinline__ void attn_key(const float* __restrict__ kr,
                                         const float* __restrict__ vr,
                                         const float4* qv, float4* o,
                                         float& m, float& z) {
    const float4* k4 = (const float4*)kr;
    const float4* v4 = (const float4*)vr;
    float s0 = 0.f, s1 = 0.f, s2 = 0.f, s3 = 0.f;
    #pragma unroll
    for (int d = 0; d < 16; d++) {
        float4 k = k4[d];
        s0 += qv[d].x * k.x; s1 += qv[d].y * k.y;
        s2 += qv[d].z * k.z; s3 += qv[d].w * k.w;
    }
    float sim = (s0 + s1) + (s2 + s3);
    if (sim > m) {
        float c = expf(m - sim);
        z *= c;
        #pragma unroll
        for (int d = 0; d < 16; d++) { o[d].x *= c; o[d].y *= c; o[d].z *= c; o[d].w *= c; }
        m = sim;
    }
    float w = expf(sim - m);
    z += w;
    #pragma unroll
    for (int d = 0; d < 16; d++) {
        float4 v = v4[d];
        o[d].x += w * v.x; o[d].y += w * v.y; o[d].z += w * v.z; o[d].w += w * v.w;
    }
}

// ============================================================================
// Light windowed attention
// ============================================================================
__global__ __launch_bounds__(256) void light_attn_kernel() {
    int unit = blockIdx.x * 4 + (threadIdx.x >> 6);
    int qi = threadIdx.x & 63;
    int w = unit & 127;
    int h = (unit >> 7) & 7;
    int b = unit >> 10;
    size_t nbase = (size_t)b * SEQ + (size_t)w * WIN;

    const float4* qp = (const float4*)(g_qkv + (nbase + qi) * 1536 + h * 64);
    float4 qv[16];
    #pragma unroll
    for (int d = 0; d < 16; d++) {
        float4 q = qp[d];
        qv[d] = make_float4(q.x * 0.125f, q.y * 0.125f, q.z * 0.125f, q.w * 0.125f);
    }
    float4 o[16];
    #pragma unroll
    for (int d = 0; d < 16; d++) o[d] = make_float4(0.f, 0.f, 0.f, 0.f);
    float m = -FLT_MAX, z = 0.f;

    int ws = (w > 0) ? -1 : 0;
    int we = (w < NW - 1) ? 1 : 0;
    for (int dw = ws; dw <= we; dw++) {
        size_t kb = (nbase + (size_t)dw * WIN) * 1536 + 512 + h * 64;
        for (int j = 0; j < WIN; j++) {
            const float* kr = g_qkv + kb + (size_t)j * 1536;
            attn_key(kr, kr + 512, qv, o, m, z);
        }
    }
    float inv = 1.0f / z;
    float4* op = (float4*)(g_lo + (nbase + qi) * HDH + h * 64);
    #pragma unroll
    for (int d = 0; d < 16; d++)
        op[d] = make_float4(o[d].x * inv, o[d].y * inv, o[d].z * inv, o[d].w * inv);
}

// ============================================================================
// Gather + rmsnorm
// ============================================================================
__global__ void gather_rms_kernel(const float* __restrict__ x,
                                  const float* __restrict__ rms_g) {
    int r = blockIdx.x;
    int tid = threadIdx.x;
    const float* src;
    float* dst;
    if (r < QROWS) {
        int b = r >> 10;
        int srcn = g_idx_q[r];
        src = x + ((size_t)b * SEQ + srcn) * DIMN;
        dst = g_xq + (size_t)r * DIMN;
    } else {
        int r2 = r - QROWS;
        int b = r2 >> 11;
        int srcn = g_idx_kv[r2];
        src = x + ((size_t)b * SEQ + srcn) * DIMN;
        dst = g_xkv + (size_t)r2 * DIMN;
    }
    int c = tid * 4;
    float4 v = *(const float4*)(src + c);
    __shared__ float red[256];
    red[tid] = v.x*v.x + v.y*v.y + v.z*v.z + v.w*v.w;
    __syncthreads();
    for (int off = 128; off; off >>= 1) { if (tid < off) red[tid] += red[tid + off]; __syncthreads(); }
    float nrm = fmaxf(sqrtf(red[0]), 1e-12f);
    float scale = 32.0f / nrm;
    float4 o;
    o.x = v.x * scale * rms_g[c+0];
    o.y = v.y * scale * rms_g[c+1];
    o.z = v.z * scale * rms_g[c+2];
    o.w = v.w * scale * rms_g[c+3];
    *(float4*)(dst + c) = o;
}

// ============================================================================
// Heavy attention
// ============================================================================
__global__ __launch_bounds__(128) void heavy_attn_kernel(const float* __restrict__ null_kv) {
    int b = blockIdx.z, h = blockIdx.y;
    int q = blockIdx.x * 128 + threadIdx.x;

    const float4* qp = (const float4*)(g_qh + ((size_t)(b * NQ + q)) * HDH + h * 64);
    float4 qv[16];
    #pragma unroll
    for (int d = 0; d < 16; d++) {
        float4 t = qp[d];
        qv[d] = make_float4(t.x * 0.125f, t.y * 0.125f, t.z * 0.125f, t.w * 0.125f);
    }
    float4 o[16];
    #pragma unroll
    for (int d = 0; d < 16; d++) o[d] = make_float4(0.f, 0.f, 0.f, 0.f);
    float m = -FLT_MAX, z = 0.f;

    attn_key(null_kv + h * 64, null_kv + HDH + h * 64, qv, o, m, z);

    for (int n = 0; n < NKV; n++) {
        const float* kr = g_kvh + ((size_t)(b * NKV + n)) * DIMN + h * 128;
        attn_key(kr, kr + 64, qv, o, m, z);
    }
    float inv = 1.0f / z;
    float4* op = (float4*)(g_oh + ((size_t)(b * NQ + q)) * HDH + h * 64);
    #pragma unroll
    for (int d = 0; d < 16; d++)
        op[d] = make_float4(o[d].x * inv, o[d].y * inv, o[d].z * inv, o[d].w * inv);
}

// ============================================================================
// Combine
// ============================================================================
__global__ void combine_kernel(float* __restrict__ out,
                               const float* __restrict__ null_q) {
    int r = blockIdx.x;
    int b = r >> 13;
    int pos = g_pos_q[r];
    int c = threadIdx.x * 4;
    float4 v = *(const float4*)(out + (size_t)r * DIMN + c);
    float4 addv;
    if (pos >= 0)
        addv = *(const float4*)(g_ho + ((size_t)(b * NQ + pos)) * DIMN + c);
    else
        addv = *(const float4*)(null_q + c);
    v.x += addv.x; v.y += addv.y; v.z += addv.z; v.w += addv.w;
    *(float4*)(out + (size_t)r * DIMN + c) = v;
}

// ============================================================================
// Launch
// ============================================================================
extern "C" void kernel_launch(void* const* d_in, const int* in_sizes, int n_in,
                              void* d_out, int out_size) {
    (void)in_sizes; (void)n_in; (void)out_size;
    const float* x       = (const float*)d_in[0];
    const float* ln_g    = (const float*)d_in[1];
    const float* ln_b    = (const float*)d_in[2];
    const float* w_qkv_l = (const float*)d_in[3];
    const float* w_out_l = (const float*)d_in[4];
    const float* null_q  = (const float*)d_in[5];
    const float* rt_q    = (const float*)d_in[6];
    const float* rt_kv   = (const float*)d_in[7];
    const float* rms_g   = (const float*)d_in[8];
    const float* w_q_h   = (const float*)d_in[9];
    const float* w_kv_h  = (const float*)d_in[10];
    const float* null_kv = (const float*)d_in[11];
    const float* w_out_h = (const float*)d_in[12];
    float* out = (float*)d_out;

    cudaFuncSetAttribute(mma_gemm_kernel, cudaFuncAttributeMaxDynamicSharedMemorySize,
                         GEMM_SMEM);

    float *xn, *qkv, *lo, *xq, *xkv, *qh, *kvh, *oh, *ho;
    __nv_bfloat16 *ahi, *alo, *bhi, *blo;
    cudaGetSymbolAddress((void**)&xn,  g_xn);
    cudaGetSymbolAddress((void**)&qkv, g_qkv);
    cudaGetSymbolAddress((void**)&lo,  g_lo);
    cudaGetSymbolAddress((void**)&xq,  g_xq);
    cudaGetSymbolAddress((void**)&xkv, g_xkv);
    cudaGetSymbolAddress((void**)&qh,  g_qh);
    cudaGetSymbolAddress((void**)&kvh, g_kvh);
    cudaGetSymbolAddress((void**)&oh,  g_oh);
    cudaGetSymbolAddress((void**)&ho,  g_ho);
    cudaGetSymbolAddress((void**)&ahi, g_ahi);
    cudaGetSymbolAddress((void**)&alo, g_alo);
    cudaGetSymbolAddress((void**)&bhi, g_bhi);
    cudaGetSymbolAddress((void**)&blo, g_blo);

    auto gemm = [&](const float* A, const float* B, float* C, int M, int N, int K) {
        int n8 = (M * K) / 8;
        convA_kernel<<<(n8 + 255) / 256, 256>>>(A, ahi, alo, n8);
        convBT_kernel<<<dim3(N / 32, K / 32), dim3(32, 8)>>>(B, bhi, blo, K, N);
        mma_gemm_kernel<<<dim3(N / 128, M / 128), 256, GEMM_SMEM>>>(
            ahi, alo, bhi, blo, C, M, N, K);
    };

    ln_kernel<<<ROWS, 256>>>(x, ln_g, ln_b);
    score_kernel<<<2048, 256>>>(x, rt_q, rt_kv);
    fill_pos_kernel<<<(BATCH * SEQ + 1023) / 1024, 1024>>>();
    coor_select_kernel<<<4, 1024>>>();

    gemm(xn, w_qkv_l, qkv, ROWS, 1536, DIMN);           // light qkv
    light_attn_kernel<<<512, 256>>>();
    gemm(lo, w_out_l, out, ROWS, DIMN, HDH);            // light out -> d_out

    gather_rms_kernel<<<QROWS + KVROWS, 256>>>(x, rms_g);
    gemm(xq, w_q_h, qh, QROWS, HDH, DIMN);              // heavy q
    gemm(xkv, w_kv_h, kvh, KVROWS, DIMN, DIMN);         // heavy kv
    heavy_attn_kernel<<<dim3(NQ / 128, HEADS, BATCH), 128>>>(null_kv);
    gemm(oh, w_out_h, ho, QROWS, DIMN, HDH);            // heavy out

    combine_kernel<<<ROWS, 256>>>(out, null_q);
}

// round 5
// speedup vs baseline: 1.9744x; 1.4650x over previous
#include <cuda_runtime.h>
#include <cuda_bf16.h>
#include <math.h>
#include <float.h>
#include <stdint.h>

// ============================================================================
// Problem constants
// ============================================================================
#define DIMN   1024
#define HEADS  8
#define DH     64
#define HDH    512
#define SEQ    8192
#define BATCH  2
#define WIN    64
#define NW     128
#define NQ     1024
#define NKV    2048
#define ROWS   (BATCH * SEQ)          // 16384
#define QROWS  (BATCH * NQ)           // 2048
#define KVROWS (BATCH * NKV)          // 4096

// ============================================================================
// Device scratch
// ============================================================================
static __device__ __align__(16) float g_xn  [(size_t)ROWS * DIMN];
static __device__ __align__(16) float g_qkv [(size_t)ROWS * 1536];
static __device__ __align__(16) float g_lo  [(size_t)ROWS * HDH];
static __device__ __align__(16) float g_s   [4 * SEQ];
static __device__             int   g_idx_q [BATCH * NQ];
static __device__             int   g_idx_kv[BATCH * NKV];
static __device__             int   g_pos_q [BATCH * SEQ];
static __device__ __align__(16) float g_xq  [(size_t)QROWS * DIMN];
static __device__ __align__(16) float g_xkv [(size_t)KVROWS * DIMN];
static __device__ __align__(16) float g_qh  [(size_t)QROWS * HDH];
static __device__ __align__(16) float g_kvh [(size_t)KVROWS * DIMN];
static __device__ __align__(16) float g_oh  [(size_t)QROWS * HDH];
static __device__ __align__(16) float g_ho  [(size_t)QROWS * DIMN];
static __device__ __align__(16) __nv_bfloat16 g_ahi[(size_t)ROWS * DIMN];
static __device__ __align__(16) __nv_bfloat16 g_alo[(size_t)ROWS * DIMN];
static __device__ __align__(16) __nv_bfloat16 g_bhi[(size_t)1536 * DIMN];
static __device__ __align__(16) __nv_bfloat16 g_blo[(size_t)1536 * DIMN];

// ============================================================================
// PTX helpers (base sm_100-safe)
// ============================================================================
__device__ __forceinline__ uint32_t smem_u32(const void* p) {
    uint32_t a;
    asm("{ .reg .u64 t; cvta.to.shared.u64 t, %1; cvt.u32.u64 %0, t; }" : "=r"(a) : "l"(p));
    return a;
}
#define LDMX4(r, addr) \
    asm volatile("ldmatrix.sync.aligned.m8n8.x4.shared.b16 {%0,%1,%2,%3}, [%4];" \
        : "=r"((r)[0]), "=r"((r)[1]), "=r"((r)[2]), "=r"((r)[3]) : "r"(addr))
#define MMA16816(d, a, b) \
    asm volatile("mma.sync.aligned.m16n8k16.row.col.f32.bf16.bf16.f32 " \
        "{%0,%1,%2,%3}, {%4,%5,%6,%7}, {%8,%9}, {%0,%1,%2,%3};" \
        : "+f"((d)[0]), "+f"((d)[1]), "+f"((d)[2]), "+f"((d)[3]) \
        : "r"((a)[0]), "r"((a)[1]), "r"((a)[2]), "r"((a)[3]), "r"((b)[0]), "r"((b)[1]))
#define CP_ASYNC16(dst, src) \
    asm volatile("cp.async.cg.shared.global [%0], [%1], 16;" :: "r"(dst), "l"(src))
#define CP_COMMIT()  asm volatile("cp.async.commit_group;")
#define CP_WAIT(n)   asm volatile("cp.async.wait_group %0;" :: "n"(n))

// ============================================================================
// fp32 -> bf16 (hi, lo) split conversions
// ============================================================================
__global__ void convA_kernel(const float* __restrict__ A,
                             __nv_bfloat16* __restrict__ hi,
                             __nv_bfloat16* __restrict__ lo, int n8) {
    int i = blockIdx.x * blockDim.x + threadIdx.x;
    if (i >= n8) return;
    float4 v0 = ((const float4*)A)[2 * i];
    float4 v1 = ((const float4*)A)[2 * i + 1];
    float v[8] = {v0.x, v0.y, v0.z, v0.w, v1.x, v1.y, v1.z, v1.w};
    __align__(16) __nv_bfloat16 h[8];
    __align__(16) __nv_bfloat16 l[8];
    #pragma unroll
    for (int j = 0; j < 8; j++) {
        h[j] = __float2bfloat16_rn(v[j]);
        l[j] = __float2bfloat16_rn(v[j] - __bfloat162float(h[j]));
    }
    ((uint4*)hi)[i] = *(const uint4*)h;
    ((uint4*)lo)[i] = *(const uint4*)l;
}

__global__ void convBT_kernel(const float* __restrict__ B,
                              __nv_bfloat16* __restrict__ hi,
                              __nv_bfloat16* __restrict__ lo, int K, int N) {
    __shared__ float t[32][33];
    int n0 = blockIdx.x * 32, k0 = blockIdx.y * 32;
    int tx = threadIdx.x, ty = threadIdx.y;
    #pragma unroll
    for (int i = ty; i < 32; i += 8)
        t[i][tx] = B[(size_t)(k0 + i) * N + n0 + tx];
    __syncthreads();
    #pragma unroll
    for (int i = ty; i < 32; i += 8) {
        float v = t[tx][i];
        __nv_bfloat16 h = __float2bfloat16_rn(v);
        __nv_bfloat16 l = __float2bfloat16_rn(v - __bfloat162float(h));
        hi[(size_t)(n0 + i) * K + k0 + tx] = h;
        lo[(size_t)(n0 + i) * K + k0 + tx] = l;
    }
}

// ============================================================================
// mma.sync bf16-split GEMM
// ============================================================================
#define KSTEP    32
#define SSTR     40
#define MATB     (128 * SSTR * 2)
#define BUFB     (4 * MATB)
#define GEMM_SMEM (2 * BUFB)

__device__ __forceinline__ void gemm_prefetch(
    const __nv_bfloat16* __restrict__ Ahi, const __nv_bfloat16* __restrict__ Alo,
    const __nv_bfloat16* __restrict__ Bhi, const __nv_bfloat16* __restrict__ Blo,
    int bm, int bn, int K, int k0, uint32_t bufbase, int tid) {
    #pragma unroll
    for (int c = tid; c < 2048; c += 256) {
        int mat = c >> 9;
        int cc  = c & 511;
        int row = cc >> 2;
        int kc  = (cc & 3) * 8;
        const __nv_bfloat16* src;
        int rbase;
        if      (mat == 0) { src = Ahi; rbase = bm; }
        else if (mat == 1) { src = Alo; rbase = bm; }
        else if (mat == 2) { src = Bhi; rbase = bn; }
        else               { src = Blo; rbase = bn; }
        const void* gsrc = src + (size_t)(rbase + row) * K + k0 + kc;
        uint32_t dst = bufbase + mat * MATB + row * (SSTR * 2) + kc * 2;
        CP_ASYNC16(dst, gsrc);
    }
    CP_COMMIT();
}

__global__ __launch_bounds__(256) void mma_gemm_kernel(
    const __nv_bfloat16* __restrict__ Ahi, const __nv_bfloat16* __restrict__ Alo,
    const __nv_bfloat16* __restrict__ Bhi, const __nv_bfloat16* __restrict__ Blo,
    float* __restrict__ C, int M, int N, int K) {
    extern __shared__ __align__(16) char smem[];
    uint32_t sb = smem_u32(smem);
    int tid = threadIdx.x;
    int lane = tid & 31, w = tid >> 5;
    int wm = w & 3, wn = w >> 2;
    int bm = blockIdx.y * 128, bn = blockIdx.x * 128;

    float acc[2][8][4];
    #pragma unroll
    for (int i = 0; i < 2; i++)
        #pragma unroll
        for (int j = 0; j < 8; j++)
            #pragma unroll
            for (int q = 0; q < 4; q++) acc[i][j][q] = 0.f;

    int a_row = lane & 15,               a_kof = (lane >> 4) * 8;
    int b_row = ((lane >> 4) & 1) * 8 + (lane & 7), b_kof = ((lane >> 3) & 1) * 8;

    gemm_prefetch(Ahi, Alo, Bhi, Blo, bm, bn, K, 0, sb, tid);
    int nt = K / KSTEP;
    for (int t = 0; t < nt; t++) {
        if (t + 1 < nt) {
            gemm_prefetch(Ahi, Alo, Bhi, Blo, bm, bn, K, (t + 1) * KSTEP,
                          sb + ((t + 1) & 1) * BUFB, tid);
            CP_WAIT(1);
        } else {
            CP_WAIT(0);
        }
        __syncthreads();
        uint32_t buf = sb + (t & 1) * BUFB;
        #pragma unroll
        for (int ks = 0; ks < 2; ks++) {
            int kk = ks * 16;
            uint32_t ah[2][4], al[2][4];
            #pragma unroll
            for (int mi = 0; mi < 2; mi++) {
                int row = wm * 32 + mi * 16 + a_row;
                uint32_t off = row * (SSTR * 2) + (kk + a_kof) * 2;
                LDMX4(ah[mi], buf + 0 * MATB + off);
                LDMX4(al[mi], buf + 1 * MATB + off);
            }
            #pragma unroll
            for (int jp = 0; jp < 4; jp++) {
                int row = wn * 64 + jp * 16 + b_row;
                uint32_t off = row * (SSTR * 2) + (kk + b_kof) * 2;
                uint32_t rh[4], rl[4];
                LDMX4(rh, buf + 2 * MATB + off);
                LDMX4(rl, buf + 3 * MATB + off);
                uint32_t bh0[2] = {rh[0], rh[1]}, bh1[2] = {rh[2], rh[3]};
                uint32_t bl0[2] = {rl[0], rl[1]}, bl1[2] = {rl[2], rl[3]};
                #pragma unroll
                for (int mi = 0; mi < 2; mi++) {
                    MMA16816(acc[mi][jp * 2    ], ah[mi], bh0);
                    MMA16816(acc[mi][jp * 2    ], ah[mi], bl0);
                    MMA16816(acc[mi][jp * 2    ], al[mi], bh0);
                    MMA16816(acc[mi][jp * 2 + 1], ah[mi], bh1);
                    MMA16816(acc[mi][jp * 2 + 1], ah[mi], bl1);
                    MMA16816(acc[mi][jp * 2 + 1], al[mi], bh1);
                }
            }
        }
        __syncthreads();
    }

    int g = lane >> 2, tig = lane & 3;
    #pragma unroll
    for (int mi = 0; mi < 2; mi++) {
        int r0 = bm + wm * 32 + mi * 16 + g;
        #pragma unroll
        for (int nj = 0; nj < 8; nj++) {
            int col = bn + wn * 64 + nj * 8 + tig * 2;
            *(float2*)(C + (size_t)r0 * N + col)       = make_float2(acc[mi][nj][0], acc[mi][nj][1]);
            *(float2*)(C + (size_t)(r0 + 8) * N + col) = make_float2(acc[mi][nj][2], acc[mi][nj][3]);
        }
    }
}

// ============================================================================
// Layernorm
// ============================================================================
__global__ void ln_kernel(const float* __restrict__ x,
                          const float* __restrict__ g,
                          const float* __restrict__ b) {
    int r = blockIdx.x;
    int tid = threadIdx.x;
    const float* row = x + (size_t)r * DIMN;
    float4 v = *(const float4*)(row + tid * 4);
    __shared__ float red[256];
    float s = v.x + v.y + v.z + v.w;
    red[tid] = s; __syncthreads();
    for (int off = 128; off; off >>= 1) { if (tid < off) red[tid] += red[tid + off]; __syncthreads(); }
    float mean = red[0] * (1.0f / DIMN);
    __syncthreads();
    float d0 = v.x - mean, d1 = v.y - mean, d2 = v.z - mean, d3 = v.w - mean;
    red[tid] = d0*d0 + d1*d1 + d2*d2 + d3*d3; __syncthreads();
    for (int off = 128; off; off >>= 1) { if (tid < off) red[tid] += red[tid + off]; __syncthreads(); }
    float var = red[0] * (1.0f / DIMN);
    float inv = 1.0f / sqrtf(var + 1e-5f);
    int c = tid * 4;
    float4 o;
    o.x = d0 * inv * g[c+0] + b[c+0];
    o.y = d1 * inv * g[c+1] + b[c+1];
    o.z = d2 * inv * g[c+2] + b[c+2];
    o.w = d3 * inv * g[c+3] + b[c+3];
    *(float4*)(g_xn + (size_t)r * DIMN + c) = o;
}

// ============================================================================
// Routing scores
// ============================================================================
__global__ void score_kernel(const float* __restrict__ x,
                             const float* __restrict__ rtq,
                             const float* __restrict__ rtkv) {
    int gw = (blockIdx.x * blockDim.x + threadIdx.x) >> 5;
    int lane = threadIdx.x & 31;
    const float* row = x + (size_t)gw * DIMN;
    float aq = 0.f, akv = 0.f;
    for (int c = lane * 4; c < DIMN; c += 128) {
        float4 xv = *(const float4*)(row + c);
        float4 q  = *(const float4*)(rtq + c);
        float4 kv = *(const float4*)(rtkv + c);
        aq  += xv.x*q.x  + xv.y*q.y  + xv.z*q.z  + xv.w*q.w;
        akv += xv.x*kv.x + xv.y*kv.y + xv.z*kv.z + xv.w*kv.w;
    }
    for (int off = 16; off; off >>= 1) {
        aq  += __shfl_down_sync(0xffffffffu, aq,  off);
        akv += __shfl_down_sync(0xffffffffu, akv, off);
    }
    if (lane == 0) {
        int b = gw >> 13, n = gw & 8191;
        g_s[(0 * 2 + b) * SEQ + n] = aq;
        g_s[(2     + b) * SEQ + n] = akv;
    }
}

__global__ void fill_pos_kernel() {
    int i = blockIdx.x * blockDim.x + threadIdx.x;
    if (i < BATCH * SEQ) g_pos_q[i] = -1;
}

// ============================================================================
// Coor-descent + deterministic top-N selection
// ============================================================================
__device__ __forceinline__ unsigned fmono(float x) {
    unsigned u = __float_as_uint(x);
    return (u & 0x80000000u) ? ~u : (u | 0x80000000u);
}
__device__ __forceinline__ int blk_reduce_sum_i(int v, int* buf, int tid) {
    buf[tid] = v; __syncthreads();
    for (int off = 512; off; off >>= 1) { if (tid < off) buf[tid] += buf[tid + off]; __syncthreads(); }
    int r = buf[0]; __syncthreads();
    return r;
}
__device__ __forceinline__ int blk_scan_excl(int v, int* buf, int tid, int* total) {
    buf[tid] = v; __syncthreads();
    for (int off = 1; off < 1024; off <<= 1) {
        int t = 0; if (tid >= off) t = buf[tid - off];
        __syncthreads();
        buf[tid] += t;
        __syncthreads();
    }
    int inc = buf[tid];
    *total = buf[1023];
    __syncthreads();
    return inc - v;
}

__global__ __launch_bounds__(1024) void coor_select_kernel() {
    int blk = blockIdx.x;
    int route = blk >> 1, b = blk & 1;
    int N = route ? NKV : NQ;
    float logk = route ? logf(2304.0f) : logf(1152.0f);
    const float* srow = g_s + (size_t)blk * SEQ;

    __shared__ float ss[SEQ];
    __shared__ float fbuf[1024];
    __shared__ int   ibuf[1024];
    int tid = threadIdx.x;
    int i0 = tid * 8;

    for (int i = tid; i < SEQ; i += 1024) ss[i] = srow[i];
    __syncthreads();

    float lm = -FLT_MAX;
    #pragma unroll
    for (int i = i0; i < i0 + 8; i++) lm = fmaxf(lm, ss[i]);
    fbuf[tid] = lm; __syncthreads();
    for (int off = 512; off; off >>= 1) { if (tid < off) fbuf[tid] = fmaxf(fbuf[tid], fbuf[tid + off]); __syncthreads(); }
    float smax = fbuf[0];
    __syncthreads();

    float a = logk - logf((float)SEQ);
    for (int it = 0; it < 49; it++) {
        float t = -a;
        float M = fminf(smax, t);
        float ls = 0.f;
        #pragma unroll
        for (int i = i0; i < i0 + 8; i++) ls += expf(fminf(ss[i], t) - M);
        fbuf[tid] = ls; __syncthreads();
        for (int off = 512; off; off >>= 1) { if (tid < off) fbuf[tid] += fbuf[tid + off]; __syncthreads(); }
        a = logk - (M + logf(fbuf[0]));
        __syncthreads();
    }

    int* idxArr = route ? &g_idx_kv[b * NKV] : &g_idx_q[b * NQ];

    int lc = 0;
    #pragma unroll
    for (int i = i0; i < i0 + 8; i++) lc += (ss[i] + a >= 0.0f);
    int C;
    int exc = blk_scan_excl(lc, ibuf, tid, &C);

    if (C >= N) {
        int r = exc;
        for (int i = i0; i < i0 + 8; i++) {
            if (ss[i] + a >= 0.0f) {
                if (r < N) { idxArr[r] = i; if (!route) g_pos_q[b * SEQ + i] = r; }
                r++;
            }
        }
    } else {
        int r = exc;
        for (int i = i0; i < i0 + 8; i++) {
            if (ss[i] + a >= 0.0f) {
                idxArr[r] = i; if (!route) g_pos_q[b * SEQ + i] = r;
                r++;
            }
        }
        int R = N - C;
        unsigned ans = 0;
        for (int bit = 31; bit >= 0; bit--) {
            unsigned cand = ans | (1u << bit);
            int c = 0;
            for (int i = i0; i < i0 + 8; i++)
                if (ss[i] + a < 0.0f && fmono(ss[i]) >= cand) c++;
            int tot = blk_reduce_sum_i(c, ibuf, tid);
            if (tot >= R) ans = cand;
        }
        int lcGT = 0;
        for (int i = i0; i < i0 + 8; i++)
            if (ss[i] + a < 0.0f && fmono(ss[i]) > ans) lcGT++;
        int totGT;
        int excGT = blk_scan_excl(lcGT, ibuf, tid, &totGT);
        {
            int rr = C + excGT;
            for (int i = i0; i < i0 + 8; i++)
                if (ss[i] + a < 0.0f && fmono(ss[i]) > ans) {
                    idxArr[rr] = i; if (!route) g_pos_q[b * SEQ + i] = rr;
                    rr++;
                }
        }
        int lcEQ = 0;
        for (int i = i0; i < i0 + 8; i++)
            if (ss[i] + a < 0.0f && fmono(ss[i]) == ans) lcEQ++;
        int totEQ;
        int excEQ = blk_scan_excl(lcEQ, ibuf, tid, &totEQ);
        int need = R - totGT;
        int r2 = excEQ;
        for (int i = i0; i < i0 + 8; i++)
            if (ss[i] + a < 0.0f && fmono(ss[i]) == ans) {
                if (r2 < need) {
                    int rank = C + totGT + r2;
                    idxArr[rank] = i; if (!route) g_pos_q[b * SEQ + i] = rank;
                }
                r2++;
            }
    }
}

// ============================================================================
// Attention v2 core: 4 threads/query, smem K/V chunks of 64 keys.
// smem layout per stage: [key][128 floats] = k(64) then v(64). 32KB/stage.
// ============================================================================
#define AT_STAGE 32768     // bytes per stage
#define AT_SMEM  (2 * AT_STAGE)

__device__ __forceinline__ void attn_process_chunk(
    const float* __restrict__ buf, int sub,
    const float4* qv, float4* o, float& m, float& z) {
    #pragma unroll 4
    for (int j = 0; j < 64; j++) {
        const float4* kp = (const float4*)(buf + j * 128 + sub * 16);
        const float4* vp = (const float4*)(buf + j * 128 + 64 + sub * 16);
        float s = 0.f;
        #pragma unroll
        for (int d = 0; d < 4; d++) {
            float4 k = kp[d];
            s += qv[d].x * k.x + qv[d].y * k.y + qv[d].z * k.z + qv[d].w * k.w;
        }
        s += __shfl_xor_sync(0xffffffffu, s, 1);
        s += __shfl_xor_sync(0xffffffffu, s, 2);
        if (s > m) {
            float c = expf(m - s);
            z *= c;
            #pragma unroll
            for (int d = 0; d < 4; d++) { o[d].x *= c; o[d].y *= c; o[d].z *= c; o[d].w *= c; }
            m = s;
        }
        float w = expf(s - m);
        z += w;
        #pragma unroll
        for (int d = 0; d < 4; d++) {
            float4 v = vp[d];
            o[d].x += w * v.x; o[d].y += w * v.y; o[d].z += w * v.z; o[d].w += w * v.w;
        }
    }
}

// ============================================================================
// Heavy attention v2: grid (NQ/64, HEADS, BATCH), 256 threads
// ============================================================================
__device__ __forceinline__ void heavy_prefetch(const float* kvbase, int kb,
                                               uint32_t dstbase, int tid) {
    #pragma unroll
    for (int i = tid; i < 2048; i += 256) {
        int key = i >> 5, part = i & 31;
        const float* src = kvbase + (size_t)(kb + key) * DIMN + part * 4;
        CP_ASYNC16(dstbase + (key * 128 + part * 4) * 4, src);
    }
    CP_COMMIT();
}

__global__ __launch_bounds__(256) void heavy_attn2_kernel(const float* __restrict__ null_kv) {
    extern __shared__ __align__(16) float sm[];
    uint32_t sb = smem_u32(sm);
    int b = blockIdx.z, h = blockIdx.y;
    int tid = threadIdx.x;
    int ql = tid >> 2, sub = tid & 3;
    int q = blockIdx.x * 64 + ql;

    const float4* qp = (const float4*)(g_qh + ((size_t)(b * NQ + q)) * HDH + h * 64 + sub * 16);
    float4 qv[4];
    #pragma unroll
    for (int d = 0; d < 4; d++) {
        float4 t = qp[d];
        qv[d] = make_float4(t.x * 0.125f, t.y * 0.125f, t.z * 0.125f, t.w * 0.125f);
    }
    float4 o[4];
    float m, z;
    {
        const float4* kp = (const float4*)(null_kv + h * 64 + sub * 16);
        const float4* vp = (const float4*)(null_kv + HDH + h * 64 + sub * 16);
        float s = 0.f;
        #pragma unroll
        for (int d = 0; d < 4; d++) {
            float4 k = kp[d];
            s += qv[d].x * k.x + qv[d].y * k.y + qv[d].z * k.z + qv[d].w * k.w;
        }
        s += __shfl_xor_sync(0xffffffffu, s, 1);
        s += __shfl_xor_sync(0xffffffffu, s, 2);
        m = s; z = 1.f;
        #pragma unroll
        for (int d = 0; d < 4; d++) o[d] = vp[d];
    }

    const float* kvbase = g_kvh + (size_t)b * NKV * DIMN + h * 128;
    const int NC = NKV / 64;           // 32 chunks
    heavy_prefetch(kvbase, 0, sb, tid);
    for (int c = 0; c < NC; c++) {
        if (c + 1 < NC) {
            heavy_prefetch(kvbase, (c + 1) * 64, sb + ((c + 1) & 1) * AT_STAGE, tid);
            CP_WAIT(1);
        } else {
            CP_WAIT(0);
        }
        __syncthreads();
        attn_process_chunk(sm + (c & 1) * (AT_STAGE / 4), sub, qv, o, m, z);
        __syncthreads();
    }
    float inv = 1.0f / z;
    float4* op = (float4*)(g_oh + ((size_t)(b * NQ + q)) * HDH + h * 64 + sub * 16);
    #pragma unroll
    for (int d = 0; d < 4; d++)
        op[d] = make_float4(o[d].x * inv, o[d].y * inv, o[d].z * inv, o[d].w * inv);
}

// ============================================================================
// Light attention v2: grid (NW, HEADS, BATCH), 256 threads
// ============================================================================
__device__ __forceinline__ void light_prefetch(const float* qkvbase, int win,
                                               int h, uint32_t dstbase, int tid) {
    #pragma unroll
    for (int i = tid; i < 2048; i += 256) {
        int key = i >> 5, part = i & 31;
        int soff = (part < 16) ? (512 + h * 64 + part * 4)
                               : (1024 + h * 64 + (part - 16) * 4);
        const float* src = qkvbase + (size_t)(win * WIN + key) * 1536 + soff;
        CP_ASYNC16(dstbase + (key * 128 + part * 4) * 4, src);
    }
    CP_COMMIT();
}

__global__ __launch_bounds__(256) void light_attn2_kernel() {
    extern __shared__ __align__(16) float sm[];
    uint32_t sb = smem_u32(sm);
    int w = blockIdx.x, h = blockIdx.y, b = blockIdx.z;
    int tid = threadIdx.x;
    int ql = tid >> 2, sub = tid & 3;
    size_t row = (size_t)b * SEQ + (size_t)w * WIN + ql;

    const float4* qp = (const float4*)(g_qkv + row * 1536 + h * 64 + sub * 16);
    float4 qv[4];
    #pragma unroll
    for (int d = 0; d < 4; d++) {
        float4 t = qp[d];
        qv[d] = make_float4(t.x * 0.125f, t.y * 0.125f, t.z * 0.125f, t.w * 0.125f);
    }
    float4 o[4];
    #pragma unroll
    for (int d = 0; d < 4; d++) o[d] = make_float4(0.f, 0.f, 0.f, 0.f);
    float m = -FLT_MAX, z = 0.f;

    const float* qkvbase = g_qkv + (size_t)b * SEQ * 1536;
    int w0 = (w > 0) ? w - 1 : 0;
    int w1 = (w < NW - 1) ? w + 1 : NW - 1;
    int nc = w1 - w0 + 1;

    light_prefetch(qkvbase, w0, h, sb, tid);
    for (int c = 0; c < nc; c++) {
        if (c + 1 < nc) {
            light_prefetch(qkvbase, w0 + c + 1, h, sb + ((c + 1) & 1) * AT_STAGE, tid);
            CP_WAIT(1);
        } else {
            CP_WAIT(0);
        }
        __syncthreads();
        attn_process_chunk(sm + (c & 1) * (AT_STAGE / 4), sub, qv, o, m, z);
        __syncthreads();
    }
    float inv = 1.0f / z;
    float4* op = (float4*)(g_lo + row * HDH + h * 64 + sub * 16);
    #pragma unroll
    for (int d = 0; d < 4; d++)
        op[d] = make_float4(o[d].x * inv, o[d].y * inv, o[d].z * inv, o[d].w * inv);
}

// ============================================================================
// Gather + rmsnorm
// ============================================================================
__global__ void gather_rms_kernel(const float* __restrict__ x,
                                  const float* __restrict__ rms_g) {
    int r = blockIdx.x;
    int tid = threadIdx.x;
    const float* src;
    float* dst;
    if (r < QROWS) {
        int b = r >> 10;
        int srcn = g_idx_q[r];
        src = x + ((size_t)b * SEQ + srcn) * DIMN;
        dst = g_xq + (size_t)r * DIMN;
    } else {
        int r2 = r - QROWS;
        int b = r2 >> 11;
        int srcn = g_idx_kv[r2];
        src = x + ((size_t)b * SEQ + srcn) * DIMN;
        dst = g_xkv + (size_t)r2 * DIMN;
    }
    int c = tid * 4;
    float4 v = *(const float4*)(src + c);
    __shared__ float red[256];
    red[tid] = v.x*v.x + v.y*v.y + v.z*v.z + v.w*v.w;
    __syncthreads();
    for (int off = 128; off; off >>= 1) { if (tid < off) red[tid] += red[tid + off]; __syncthreads(); }
    float nrm = fmaxf(sqrtf(red[0]), 1e-12f);
    float scale = 32.0f / nrm;
    float4 o;
    o.x = v.x * scale * rms_g[c+0];
    o.y = v.y * scale * rms_g[c+1];
    o.z = v.z * scale * rms_g[c+2];
    o.w = v.w * scale * rms_g[c+3];
    *(float4*)(dst + c) = o;
}

// ============================================================================
// Combine
// ============================================================================
__global__ void combine_kernel(float* __restrict__ out,
                               const float* __restrict__ null_q) {
    int r = blockIdx.x;
    int b = r >> 13;
    int pos = g_pos_q[r];
    int c = threadIdx.x * 4;
    float4 v = *(const float4*)(out + (size_t)r * DIMN + c);
    float4 addv;
    if (pos >= 0)
        addv = *(const float4*)(g_ho + ((size_t)(b * NQ + pos)) * DIMN + c);
    else
        addv = *(const float4*)(null_q + c);
    v.x += addv.x; v.y += addv.y; v.z += addv.z; v.w += addv.w;
    *(float4*)(out + (size_t)r * DIMN + c) = v;
}

// ============================================================================
// Launch
// ============================================================================
extern "C" void kernel_launch(void* const* d_in, const int* in_sizes, int n_in,
                              void* d_out, int out_size) {
    (void)in_sizes; (void)n_in; (void)out_size;
    const float* x       = (const float*)d_in[0];
    const float* ln_g    = (const float*)d_in[1];
    const float* ln_b    = (const float*)d_in[2];
    const float* w_qkv_l = (const float*)d_in[3];
    const float* w_out_l = (const float*)d_in[4];
    const float* null_q  = (const float*)d_in[5];
    const float* rt_q    = (const float*)d_in[6];
    const float* rt_kv   = (const float*)d_in[7];
    const float* rms_g   = (const float*)d_in[8];
    const float* w_q_h   = (const float*)d_in[9];
    const float* w_kv_h  = (const float*)d_in[10];
    const float* null_kv = (const float*)d_in[11];
    const float* w_out_h = (const float*)d_in[12];
    float* out = (float*)d_out;

    cudaFuncSetAttribute(mma_gemm_kernel, cudaFuncAttributeMaxDynamicSharedMemorySize,
                         GEMM_SMEM);
    cudaFuncSetAttribute(heavy_attn2_kernel, cudaFuncAttributeMaxDynamicSharedMemorySize,
                         AT_SMEM);
    cudaFuncSetAttribute(light_attn2_kernel, cudaFuncAttributeMaxDynamicSharedMemorySize,
                         AT_SMEM);

    float *xn, *qkv, *lo, *xq, *xkv, *qh, *kvh, *oh, *ho;
    __nv_bfloat16 *ahi, *alo, *bhi, *blo;
    cudaGetSymbolAddress((void**)&xn,  g_xn);
    cudaGetSymbolAddress((void**)&qkv, g_qkv);
    cudaGetSymbolAddress((void**)&lo,  g_lo);
    cudaGetSymbolAddress((void**)&xq,  g_xq);
    cudaGetSymbolAddress((void**)&xkv, g_xkv);
    cudaGetSymbolAddress((void**)&qh,  g_qh);
    cudaGetSymbolAddress((void**)&kvh, g_kvh);
    cudaGetSymbolAddress((void**)&oh,  g_oh);
    cudaGetSymbolAddress((void**)&ho,  g_ho);
    cudaGetSymbolAddress((void**)&ahi, g_ahi);
    cudaGetSymbolAddress((void**)&alo, g_alo);
    cudaGetSymbolAddress((void**)&bhi, g_bhi);
    cudaGetSymbolAddress((void**)&blo, g_blo);

    auto gemm = [&](const float* A, const float* B, float* C, int M, int N, int K) {
        int n8 = (M * K) / 8;
        convA_kernel<<<(n8 + 255) / 256, 256>>>(A, ahi, alo, n8);
        convBT_kernel<<<dim3(N / 32, K / 32), dim3(32, 8)>>>(B, bhi, blo, K, N);
        mma_gemm_kernel<<<dim3(N / 128, M / 128), 256, GEMM_SMEM>>>(
            ahi, alo, bhi, blo, C, M, N, K);
    };

    ln_kernel<<<ROWS, 256>>>(x, ln_g, ln_b);
    score_kernel<<<2048, 256>>>(x, rt_q, rt_kv);
    fill_pos_kernel<<<(BATCH * SEQ + 1023) / 1024, 1024>>>();
    coor_select_kernel<<<4, 1024>>>();

    gemm(xn, w_qkv_l, qkv, ROWS, 1536, DIMN);           // light qkv
    light_attn2_kernel<<<dim3(NW, HEADS, BATCH), 256, AT_SMEM>>>();
    gemm(lo, w_out_l, out, ROWS, DIMN, HDH);            // light out -> d_out

    gather_rms_kernel<<<QROWS + KVROWS, 256>>>(x, rms_g);
    gemm(xq, w_q_h, qh, QROWS, HDH, DIMN);              // heavy q
    gemm(xkv, w_kv_h, kvh, KVROWS, DIMN, DIMN);         // heavy kv
    heavy_attn2_kernel<<<dim3(NQ / 64, HEADS, BATCH), 256, AT_SMEM>>>(null_kv);
    gemm(oh, w_out_h, ho, QROWS, DIMN, HDH);            // heavy out

    combine_kernel<<<ROWS, 256>>>(out, null_q);
}